// round 5
// baseline (speedup 1.0000x reference)
#include <cuda_runtime.h>
#include <cuda_bf16.h>

#define T_LEN 4096
#define E_DIM 256
#define H_DIM 10
#define G_DIM 40           // 4*H
#define O_DIM 50257
#define NB    128          // fused-kernel grid
#define OC_TILES 50        // ceil(O_DIM/1024)
#define TC_TILES 64        // T_LEN/64
#define N_TILES  (OC_TILES * TC_TILES)

// Scratch (static device globals: no allocation allowed)
// g_xg layout per t: 40 floats: [half][unit j][gate-in-pair]
//   half 0: (i_j, f_j) at floats [2j, 2j+1]
//   half 1: (g_j, o_j) at floats [20+2j, 20+2j+1]
__device__ float g_xg[(T_LEN + 8) * G_DIM];   // padded for prefetch overrun
__device__ float g_hs[T_LEN * H_DIM];
__device__ int   g_progress;

// ---------------------------------------------------------------------------
// packed f32x2 + HW tanh helpers
// ---------------------------------------------------------------------------
typedef unsigned long long u64;

__device__ __forceinline__ u64 pack2_(float lo, float hi) {
    u64 r; asm("mov.b64 %0, {%1, %2};" : "=l"(r) : "f"(lo), "f"(hi)); return r;
}
__device__ __forceinline__ void unpack2_(u64 v, float& lo, float& hi) {
    asm("mov.b64 {%0, %1}, %2;" : "=f"(lo), "=f"(hi) : "l"(v));
}
__device__ __forceinline__ u64 fma2_(u64 a, u64 b, u64 c) {
    u64 d; asm("fma.rn.f32x2 %0, %1, %2, %3;" : "=l"(d) : "l"(a), "l"(b), "l"(c));
    return d;
}
__device__ __forceinline__ u64 add2_(u64 a, u64 b) {
    u64 d; asm("add.rn.f32x2 %0, %1, %2;" : "=l"(d) : "l"(a), "l"(b));
    return d;
}
__device__ __forceinline__ u64 mul2_(u64 a, u64 b) {
    u64 d; asm("mul.rn.f32x2 %0, %1, %2;" : "=l"(d) : "l"(a), "l"(b));
    return d;
}
__device__ __forceinline__ float tanhap_(float x) {
    float y; asm("tanh.approx.f32 %0, %1;" : "=f"(y) : "f"(x)); return y;
}

// ---------------------------------------------------------------------------
// Kernel 1: xg = emb @ w_ih^T + b_ih + b_hh, written in the scan's layout.
// warp == gate g (0..3); handles units r = 0..9.
// slot for (gate g, unit r): (g>>1)*20 + 2*r + (g&1)
// ---------------------------------------------------------------------------
__global__ void __launch_bounds__(128) k_embed_gates(
    const int* __restrict__ x, const float* __restrict__ emb,
    const float* __restrict__ w_ih, const float* __restrict__ b_ih,
    const float* __restrict__ b_hh)
{
    if (blockIdx.x == 0 && threadIdx.x == 0) g_progress = 0;

    const int t    = blockIdx.x;
    const int lane = threadIdx.x & 31;
    const int gate = threadIdx.x >> 5;        // 0..3
    const float* erow = emb + (long)x[t] * E_DIM;

    float acc[10];
#pragma unroll
    for (int r = 0; r < 10; r++) acc[r] = 0.f;

#pragma unroll
    for (int i = 0; i < E_DIM / 32; i++) {
        const int e  = lane + i * 32;
        const float ev = __ldg(erow + e);
#pragma unroll
        for (int r = 0; r < 10; r++)
            acc[r] = fmaf(ev, __ldg(w_ih + (gate * 10 + r) * E_DIM + e), acc[r]);
    }
#pragma unroll
    for (int r = 0; r < 10; r++) {
        float v = acc[r];
#pragma unroll
        for (int s = 16; s > 0; s >>= 1) v += __shfl_xor_sync(0xffffffffu, v, s);
        if (lane == 0) {
            const int row  = gate * 10 + r;
            const int slot = (gate >> 1) * 20 + 2 * r + (gate & 1);
            g_xg[t * G_DIM + slot] = v + b_ih[row] + b_hh[row];
        }
    }
}

// ---------------------------------------------------------------------------
// Fused kernel:
//   block 0 / warp 0 : sequential LSTM scan (20 active lanes), publishes
//                      progress every 64 steps
//   blocks 1..NB-1   : stream output tiles (64 t x 1024 vocab) as hs arrives
// ---------------------------------------------------------------------------
__global__ void __launch_bounds__(256) k_fused(
    const float* __restrict__ w_hh,
    const float* __restrict__ W, const float* __restrict__ bo,
    float* __restrict__ out)
{
    __shared__ u64 hbuf[2][12];          // (h,h) pairs, double-buffered

    if (blockIdx.x == 0) {
        // ============================ PRODUCER ============================
        if (threadIdx.x >= 32) return;
        const int L    = threadIdx.x;
        const int j    = (L < 20) ? (L % 10) : 0;
        const int half = (L < 20) ? (L / 10) : 0;
        const int gA   = 2 * half;           // gate A row base: i or g
        const int gB   = 2 * half + 1;       // gate B: f or o
        const int slot = half * 10 + j;      // u64 slot within a timestep
        const int pidx = (L < 10) ? (L + 10) : ((L < 20) ? (L - 10) : L);

        // packed recurrent weights: wp[k] = (w_gA[j][k], w_gB[j][k])
        u64 wp[H_DIM];
#pragma unroll
        for (int k = 0; k < H_DIM; k++)
            wp[k] = pack2_(w_hh[(gA * H_DIM + j) * H_DIM + k],
                           w_hh[(gB * H_DIM + j) * H_DIM + k]);

        // activation constants: act = post_m * tanh(pre * x) + post_b
        // sigmoid: pre .5, m .5, b .5 ; tanh: pre 1, m 1, b 0
        const u64 pre2  = pack2_(half ? 1.0f : 0.5f, 0.5f);
        const u64 postM = pack2_(half ? 1.0f : 0.5f, 0.5f);
        const u64 postB = pack2_(half ? 0.0f : 0.5f, 0.5f);

        if (L < 12) { hbuf[0][L] = 0ull; hbuf[1][L] = 0ull; }
        __syncwarp();

        const u64* __restrict__ xg64 = (const u64*)g_xg;
        u64 cur0 = xg64[0 * 20 + slot];
        u64 cur1 = xg64[1 * 20 + slot];

        float c = 0.f;

#define LSTM_STEP(CUR, TIDX, RB, WB)                                          \
        do {                                                                  \
            const ulonglong2 h01 = *(const ulonglong2*)&hbuf[RB][0];          \
            const ulonglong2 h23 = *(const ulonglong2*)&hbuf[RB][2];          \
            const ulonglong2 h45 = *(const ulonglong2*)&hbuf[RB][4];          \
            const ulonglong2 h67 = *(const ulonglong2*)&hbuf[RB][6];          \
            const ulonglong2 h89 = *(const ulonglong2*)&hbuf[RB][8];          \
            u64 a = CUR, b = 0ull;                                            \
            a = fma2_(h01.x, wp[0], a);  b = fma2_(h01.y, wp[1], b);          \
            a = fma2_(h23.x, wp[2], a);  b = fma2_(h23.y, wp[3], b);          \
            a = fma2_(h45.x, wp[4], a);  b = fma2_(h45.y, wp[5], b);          \
            a = fma2_(h67.x, wp[6], a);  b = fma2_(h67.y, wp[7], b);          \
            a = fma2_(h89.x, wp[8], a);  b = fma2_(h89.y, wp[9], b);          \
            const u64 pre = mul2_(add2_(a, b), pre2);                         \
            float p0, p1;  unpack2_(pre, p0, p1);                             \
            const u64 tp  = pack2_(tanhap_(p0), tanhap_(p1));                 \
            const u64 act = fma2_(tp, postM, postB);                          \
            float aA, aB;  unpack2_(act, aA, aB);                             \
            const float rA = __shfl_sync(0xffffffffu, aA, pidx);              \
            const float rB = __shfl_sync(0xffffffffu, aB, pidx);              \
            /* lanes 0-9: i_=aA f_=aB g_=rA o_=rB */                          \
            c = fmaf(aB, c, aA * rA);                                         \
            const float h = rB * tanhap_(c);                                  \
            if (L < 10) {                                                     \
                hbuf[WB][j] = pack2_(h, h);                                   \
                g_hs[(TIDX) * H_DIM + j] = h;                                 \
            }                                                                 \
            __syncwarp();                                                     \
        } while (0)

        for (int tb = 0; tb < T_LEN; tb += 64) {
#pragma unroll 1
            for (int t = tb; t < tb + 64; t += 2) {
                LSTM_STEP(cur0, t,     0, 1);
                cur0 = xg64[(t + 2) * 20 + slot];
                LSTM_STEP(cur1, t + 1, 1, 0);
                cur1 = xg64[(t + 3) * 20 + slot];
            }
            if (L == 0) {
                int done = tb + 64;   // syncwarp in step orders lanes' stores
                asm volatile("st.release.gpu.b32 [%0], %1;"
                             :: "l"(&g_progress), "r"(done) : "memory");
            }
        }
#undef LSTM_STEP
        return;
    }

    // ============================== CONSUMERS ==============================
    const int tid = threadIdx.x;
    __shared__ float hsh[64 * H_DIM];

    for (int tile = blockIdx.x - 1; tile < N_TILES; tile += NB - 1) {
        const int tc = tile / OC_TILES;
        const int oc = tile % OC_TILES;
        const int need = (tc + 1) * 64;

        // preload this tile's W rows + bias while (possibly) waiting
        const int obase = oc * 1024 + tid;
        float w[4][H_DIM];
        float bb[4];
        bool  valid[4];
#pragma unroll
        for (int q = 0; q < 4; q++) {
            const int o = obase + q * 256;
            valid[q] = (o < O_DIM);
            bb[q] = valid[q] ? __ldg(bo + o) : 0.f;
#pragma unroll
            for (int k = 0; k < H_DIM; k++)
                w[q][k] = valid[q] ? __ldg(W + (long)o * H_DIM + k) : 0.f;
        }

        __syncthreads();   // protect smem reuse from previous tile
        if (tid == 0) {
            int p;
            while (true) {
                asm volatile("ld.acquire.gpu.b32 %0, [%1];"
                             : "=r"(p) : "l"(&g_progress) : "memory");
                if (p >= need) break;
                __nanosleep(256);
            }
        }
        __syncthreads();

        for (int i = tid; i < 64 * H_DIM; i += 256)
            hsh[i] = g_hs[tc * 64 * H_DIM + i];
        __syncthreads();

        const int t0 = tc * 64;
        for (int tt = 0; tt < 64; tt++) {
            float hv[H_DIM];
#pragma unroll
            for (int k = 0; k < H_DIM; k++) hv[k] = hsh[tt * H_DIM + k];
            const long rowoff = (long)(t0 + tt) * O_DIM;
#pragma unroll
            for (int q = 0; q < 4; q++) {
                float acc = bb[q];
#pragma unroll
                for (int k = 0; k < H_DIM; k++)
                    acc = fmaf(hv[k], w[q][k], acc);
                if (valid[q]) out[rowoff + obase + q * 256] = acc;
            }
        }
    }
}

// ---------------------------------------------------------------------------
extern "C" void kernel_launch(void* const* d_in, const int* in_sizes, int n_in,
                              void* d_out, int out_size)
{
    const int*   x    = (const int*)  d_in[0];
    const float* emb  = (const float*)d_in[1];
    const float* w_ih = (const float*)d_in[2];
    const float* w_hh = (const float*)d_in[3];
    const float* b_ih = (const float*)d_in[4];
    const float* b_hh = (const float*)d_in[5];
    const float* Wout = (const float*)d_in[6];
    const float* bout = (const float*)d_in[7];
    float* out = (float*)d_out;

    k_embed_gates<<<T_LEN, 128>>>(x, emb, w_ih, b_ih, b_hh);
    k_fused<<<NB, 256>>>(w_hh, Wout, bout, out);
}